// round 1
// baseline (speedup 1.0000x reference)
#include <cuda_runtime.h>
#include <stdint.h>

// Problem constants
#define B      128
#define D      512
#define M      262144
#define K_TOP  256

// Output layout: [topk_feat | topk_score | topk_index(as float)]
#define FEAT_ELEMS  ((size_t)B * K_TOP * D)   // 16777216
#define SCORE_OFF   FEAT_ELEMS
#define IDX_OFF     (FEAT_ELEMS + (size_t)B * K_TOP)

// Scratch (static device globals — no runtime allocation allowed)
__device__ float g_qn[B * D];
__device__ float g_scores[(size_t)B * M];     // 128 MB
__device__ int   g_topk_idx[B * K_TOP];

// ---------------------------------------------------------------------------
// Kernel 1: L2-normalize query rows
// ---------------------------------------------------------------------------
__global__ void normalize_kernel(const float* __restrict__ q) {
    int b = blockIdx.x;
    int tid = threadIdx.x;  // 128 threads
    const float* row = q + b * D;
    float s = 0.f;
    for (int i = tid; i < D; i += 128) {
        float v = row[i];
        s += v * v;
    }
    #pragma unroll
    for (int o = 16; o > 0; o >>= 1) s += __shfl_xor_sync(0xffffffffu, s, o);
    __shared__ float ws[4];
    if ((tid & 31) == 0) ws[tid >> 5] = s;
    __syncthreads();
    float tot = ws[0] + ws[1] + ws[2] + ws[3];
    float inv = rsqrtf(tot);
    for (int i = tid; i < D; i += 128) g_qn[b * D + i] = row[i] * inv;
}

// ---------------------------------------------------------------------------
// Kernel 2: fp32 SGEMM  scores[b][m] = dot(qn[b], sk[m])
// Tile: 128 keys (M) x 128 batch (all of B) x 32 K. 256 threads, 8x8/thread.
// ---------------------------------------------------------------------------
#define TM 128
#define TK 32

__global__ __launch_bounds__(256) void gemm_kernel(const float* __restrict__ sk) {
    __shared__ float sK[TK][TM + 4];  // sK[k][m]
    __shared__ float sQ[TK][B + 4];   // sQ[k][b]
    const int m0 = blockIdx.x * TM;
    const int tid = threadIdx.x;
    const int tx = tid & 15;   // m direction
    const int ty = tid >> 4;   // b direction

    float acc[8][8];
    #pragma unroll
    for (int i = 0; i < 8; i++)
        #pragma unroll
        for (int j = 0; j < 8; j++) acc[i][j] = 0.f;

    for (int k0 = 0; k0 < D; k0 += TK) {
        // Load SK tile [128 rows x 32 k] transposed into sK
        #pragma unroll
        for (int it = 0; it < 4; it++) {
            int i = tid + it * 256;           // 0..1023  (1024 float4)
            int row = i >> 3;
            int c4  = i & 7;
            float4 v = *(const float4*)(sk + (size_t)(m0 + row) * D + k0 + c4 * 4);
            sK[c4 * 4 + 0][row] = v.x;
            sK[c4 * 4 + 1][row] = v.y;
            sK[c4 * 4 + 2][row] = v.z;
            sK[c4 * 4 + 3][row] = v.w;
        }
        // Load Q tile [128 rows x 32 k] transposed into sQ
        #pragma unroll
        for (int it = 0; it < 4; it++) {
            int i = tid + it * 256;
            int row = i >> 3;
            int c4  = i & 7;
            float4 v = *(const float4*)(g_qn + row * D + k0 + c4 * 4);
            sQ[c4 * 4 + 0][row] = v.x;
            sQ[c4 * 4 + 1][row] = v.y;
            sQ[c4 * 4 + 2][row] = v.z;
            sQ[c4 * 4 + 3][row] = v.w;
        }
        __syncthreads();

        #pragma unroll
        for (int kk = 0; kk < TK; kk++) {
            float fm[8], fb[8];
            #pragma unroll
            for (int i = 0; i < 8; i++) fm[i] = sK[kk][tx * 8 + i];
            #pragma unroll
            for (int i = 0; i < 8; i++) fb[i] = sQ[kk][ty * 8 + i];
            #pragma unroll
            for (int bi = 0; bi < 8; bi++)
                #pragma unroll
                for (int mi = 0; mi < 8; mi++)
                    acc[bi][mi] = fmaf(fb[bi], fm[mi], acc[bi][mi]);
        }
        __syncthreads();
    }

    #pragma unroll
    for (int bi = 0; bi < 8; bi++) {
        int b = ty * 8 + bi;
        float* dst = g_scores + (size_t)b * M + m0 + tx * 8;
        #pragma unroll
        for (int q4 = 0; q4 < 2; q4++) {
            float4 v = make_float4(acc[bi][q4 * 4 + 0], acc[bi][q4 * 4 + 1],
                                   acc[bi][q4 * 4 + 2], acc[bi][q4 * 4 + 3]);
            *(float4*)(dst + q4 * 4) = v;
        }
    }
}

// ---------------------------------------------------------------------------
// Kernel 3: per-row exact top-256 via byte-wise radix select + bitonic sort
// ---------------------------------------------------------------------------
__device__ __forceinline__ unsigned mono(float f) {
    unsigned b = __float_as_uint(f);
    return (b & 0x80000000u) ? ~b : (b | 0x80000000u);
}
__device__ __forceinline__ float inv_mono(unsigned u) {
    unsigned b = (u & 0x80000000u) ? (u & 0x7FFFFFFFu) : ~u;
    return __uint_as_float(b);
}

#define NT 1024

__global__ __launch_bounds__(NT) void topk_kernel(float* __restrict__ out) {
    const int b = blockIdx.x;
    const int tid = threadIdx.x;
    const float* row = g_scores + (size_t)b * M;

    __shared__ unsigned hist[256];
    __shared__ unsigned s_pref;
    __shared__ int s_r;
    __shared__ unsigned s_cnt;
    __shared__ unsigned long long keys[512];

    unsigned prefix = 0;
    int r = K_TOP;

    for (int shift = 24; shift >= 0; shift -= 8) {
        if (tid < 256) hist[tid] = 0;
        __syncthreads();
        unsigned himask = (shift == 24) ? 0u : (0xFFFFFFFFu << (shift + 8));
        for (int i = tid; i < M; i += NT) {
            unsigned u = mono(row[i]);
            if ((u & himask) == (prefix & himask))
                atomicAdd(&hist[(u >> shift) & 0xFFu], 1u);
        }
        __syncthreads();
        if (tid == 0) {
            int c = 0;
            int bsel = 0;
            for (int bb = 255; bb >= 0; bb--) {
                int h = (int)hist[bb];
                if (c + h >= r) { bsel = bb; s_r = r - c; break; }
                c += h;
            }
            s_pref = prefix | ((unsigned)bsel << shift);
        }
        __syncthreads();
        prefix = s_pref;
        r = s_r;
        __syncthreads();
    }

    // prefix == exact monotone key of the rank-256 element
    if (tid == 0) s_cnt = 0;
    __syncthreads();
    const unsigned T = prefix;
    for (int i = tid; i < M; i += NT) {
        unsigned u = mono(row[i]);
        if (u >= T) {
            unsigned p = atomicAdd(&s_cnt, 1u);
            if (p < 512u)
                keys[p] = ((unsigned long long)u << 32) |
                          (unsigned long long)(0xFFFFFFFFu - (unsigned)i);
        }
    }
    __syncthreads();
    unsigned n = s_cnt;
    if (n > 512u) n = 512u;
    for (int i = tid; i < 512; i += NT)
        if (i >= (int)n) keys[i] = 0ull;
    __syncthreads();

    // Bitonic sort, descending (key = score-bits desc, then index asc)
    for (int size = 2; size <= 512; size <<= 1) {
        for (int stride = size >> 1; stride > 0; stride >>= 1) {
            if (tid < 256) {
                int i = 2 * tid - (tid & (stride - 1));
                int j = i + stride;
                bool desc = ((i & size) == 0);
                unsigned long long a = keys[i], c = keys[j];
                bool sw = desc ? (a < c) : (a > c);
                if (sw) { keys[i] = c; keys[j] = a; }
            }
            __syncthreads();
        }
    }

    for (int k = tid; k < K_TOP; k += NT) {
        unsigned long long key = keys[k];
        unsigned u   = (unsigned)(key >> 32);
        unsigned idx = 0xFFFFFFFFu - (unsigned)(key & 0xFFFFFFFFu);
        out[SCORE_OFF + (size_t)b * K_TOP + k] = inv_mono(u);
        out[IDX_OFF   + (size_t)b * K_TOP + k] = (float)idx;
        g_topk_idx[b * K_TOP + k] = (int)idx;
    }
}

// ---------------------------------------------------------------------------
// Kernel 4: gather color_value rows for the selected indices
// ---------------------------------------------------------------------------
__global__ void gather_kernel(const float* __restrict__ cv, float* __restrict__ out) {
    int k = blockIdx.x;
    int b = blockIdx.y;
    int idx = g_topk_idx[b * K_TOP + k];
    const float4* src = (const float4*)(cv + (size_t)idx * D);
    float4* dst = (float4*)(out + ((size_t)b * K_TOP + k) * D);
    dst[threadIdx.x] = src[threadIdx.x];  // 128 threads x float4 = 512 floats
}

// ---------------------------------------------------------------------------
extern "C" void kernel_launch(void* const* d_in, const int* in_sizes, int n_in,
                              void* d_out, int out_size) {
    const float* q  = (const float*)d_in[0];  // query       [128, 512]
    const float* sk = (const float*)d_in[1];  // spatial_key [262144, 512]
    const float* cv = (const float*)d_in[2];  // color_value [262144, 512]
    float* out = (float*)d_out;

    normalize_kernel<<<B, 128>>>(q);
    gemm_kernel<<<M / TM, 256>>>(sk);
    topk_kernel<<<B, NT>>>(out);
    gather_kernel<<<dim3(K_TOP, B), 128>>>(cv, out);
}